// round 1
// baseline (speedup 1.0000x reference)
#include <cuda_runtime.h>
#include <math.h>

#define B_    4
#define S_    1024
#define DIM_  2048
#define NH_   32
#define NKV_  8
#define HD_   64
#define ASH_  3072     // (32 + 2*8) * 64
#define MTOT_ 4096     // B_ * S_

// Scratch (allocation-free: __device__ globals)
__device__ float g_qkv[MTOT_ * ASH_];   // 48 MB: [m][g*384 + slot*64 + d]
__device__ float g_o[MTOT_ * DIM_];     // 32 MB: attention out [m][h*64 + d]

// ---------------------------------------------------------------------------
// SGEMM (NT): C[m][n] = sum_d A[m][d] * B[n][d].  Both operands K-major.
// 128x128 block, BK=8, 256 threads, 8x8 microtile. Smem tiles stored
// transposed [k][m] with stride 132 => conflict-free stores and loads.
// ---------------------------------------------------------------------------
__global__ __launch_bounds__(256) void sgemm_nt(
    const float* __restrict__ A, const float* __restrict__ B,
    float* __restrict__ C, int N, int K) {
  __shared__ float As[8][132];
  __shared__ float Bs[8][132];
  const int tid = threadIdx.x;
  const int ty = tid >> 4, tx = tid & 15;
  const int m0 = blockIdx.y * 128, n0 = blockIdx.x * 128;
  const int lr = tid >> 1, lh = tid & 1;
  const float* Ap = A + (size_t)(m0 + lr) * K + lh * 4;
  const float* Bp = B + (size_t)(n0 + lr) * K + lh * 4;

  float acc[8][8];
#pragma unroll
  for (int i = 0; i < 8; i++)
#pragma unroll
    for (int j = 0; j < 8; j++) acc[i][j] = 0.f;

  for (int k0 = 0; k0 < K; k0 += 8) {
    float4 av = *(const float4*)(Ap + k0);
    float4 bv = *(const float4*)(Bp + k0);
    As[lh * 4 + 0][lr] = av.x; As[lh * 4 + 1][lr] = av.y;
    As[lh * 4 + 2][lr] = av.z; As[lh * 4 + 3][lr] = av.w;
    Bs[lh * 4 + 0][lr] = bv.x; Bs[lh * 4 + 1][lr] = bv.y;
    Bs[lh * 4 + 2][lr] = bv.z; Bs[lh * 4 + 3][lr] = bv.w;
    __syncthreads();
#pragma unroll
    for (int k = 0; k < 8; k++) {
      float4 a0 = *(const float4*)&As[k][ty * 8];
      float4 a1 = *(const float4*)&As[k][ty * 8 + 4];
      float4 b0 = *(const float4*)&Bs[k][tx * 8];
      float4 b1 = *(const float4*)&Bs[k][tx * 8 + 4];
      float a[8] = {a0.x, a0.y, a0.z, a0.w, a1.x, a1.y, a1.z, a1.w};
      float bb[8] = {b0.x, b0.y, b0.z, b0.w, b1.x, b1.y, b1.z, b1.w};
#pragma unroll
      for (int i = 0; i < 8; i++)
#pragma unroll
        for (int j = 0; j < 8; j++)
          acc[i][j] = fmaf(a[i], bb[j], acc[i][j]);
    }
    __syncthreads();
  }

#pragma unroll
  for (int i = 0; i < 8; i++) {
    float* Cp = C + (size_t)(m0 + ty * 8 + i) * N + n0 + tx * 8;
    float4 c0 = {acc[i][0], acc[i][1], acc[i][2], acc[i][3]};
    float4 c1 = {acc[i][4], acc[i][5], acc[i][6], acc[i][7]};
    *(float4*)Cp = c0;
    *(float4*)(Cp + 4) = c1;
  }
}

// ---------------------------------------------------------------------------
// RoPE in-place on q (slots 0..3) and k (slot 4) of g_qkv.
// One thread = one (even,odd) pair.
// ---------------------------------------------------------------------------
__global__ void rope_kernel(float* __restrict__ qkv,
                            const float* __restrict__ cs,
                            const float* __restrict__ sn) {
  int p = blockIdx.x * blockDim.x + threadIdx.x;
  if (p >= MTOT_ * 40 * 32) return;
  int i = p & 31;
  int hh = (p >> 5) % 40;
  int m = p / (40 * 32);
  int s = m & (S_ - 1);
  int g = hh / 5, j = hh - g * 5;    // j in [0,4]: 0..3 = q slots, 4 = k
  size_t base = (size_t)m * ASH_ + g * 384 + j * 64 + 2 * i;
  float2 v = *(float2*)(qkv + base);
  float c = cs[s * 32 + i], si = sn[s * 32 + i];
  float2 o;
  o.x = v.x * c - v.y * si;
  o.y = v.x * si + v.y * c;
  *(float2*)(qkv + base) = o;
}

// ---------------------------------------------------------------------------
// Flash attention (causal, GQA). Block = (q_tile 128 rows, head, batch).
// 256 threads = 16(ty: 8 rows each) x 16(tx: 4 cols each).
// K tile = 64 cols. Online softmax; row stats reduced via 16-lane shfl.
// ---------------------------------------------------------------------------
__global__ __launch_bounds__(256) void flash_attn(
    const float* __restrict__ qkv, float* __restrict__ o) {
  extern __shared__ float sm[];
  float* Qst = sm;                            // [64][132] d-major (transposed)
  float* Kst = sm + 64 * 132;                 // [64][68]  d-major
  float* Vs  = sm + 64 * 132 + 64 * 68;       // [64][68]  k-major (natural)
  float* Pst = sm + 64 * 132 + 2 * 64 * 68;   // [64][132] k-major (transposed)

  const int qt = blockIdx.x, h = blockIdx.y, b = blockIdx.z;
  const int g = h >> 2;
  const float* qb = qkv + (size_t)b * S_ * ASH_ + g * 384 + (h & 3) * 64;
  const float* kb = qkv + (size_t)b * S_ * ASH_ + g * 384 + 256;
  const float* vb = qkv + (size_t)b * S_ * ASH_ + g * 384 + 320;
  const int tid = threadIdx.x;
  const int ty = tid >> 4, tx = tid & 15;
  const int r0 = qt * 128;

  // Load Q tile transposed (pre-scaled by 1/sqrt(64))
  for (int f = tid; f < 128 * 16; f += 256) {
    int row = f >> 4, d4 = f & 15;
    float4 v = *(const float4*)(qb + (size_t)(r0 + row) * ASH_ + d4 * 4);
    Qst[(d4 * 4 + 0) * 132 + row] = v.x * 0.125f;
    Qst[(d4 * 4 + 1) * 132 + row] = v.y * 0.125f;
    Qst[(d4 * 4 + 2) * 132 + row] = v.z * 0.125f;
    Qst[(d4 * 4 + 3) * 132 + row] = v.w * 0.125f;
  }

  float m_run[8], l_run[8], Oa[8][4];
#pragma unroll
  for (int i = 0; i < 8; i++) {
    m_run[i] = -1e30f;
    l_run[i] = 0.f;
#pragma unroll
    for (int j = 0; j < 4; j++) Oa[i][j] = 0.f;
  }

  const int nkt = 2 * qt + 2;   // causal: only tiles overlapping the triangle
  for (int kt = 0; kt < nkt; kt++) {
    __syncthreads();   // guards Q store (first iter) / K,V,P reuse (later)
    for (int f = tid; f < 64 * 16; f += 256) {
      int c = f >> 4, d4 = f & 15;
      float4 kv4 = *(const float4*)(kb + (size_t)(kt * 64 + c) * ASH_ + d4 * 4);
      Kst[(d4 * 4 + 0) * 68 + c] = kv4.x;
      Kst[(d4 * 4 + 1) * 68 + c] = kv4.y;
      Kst[(d4 * 4 + 2) * 68 + c] = kv4.z;
      Kst[(d4 * 4 + 3) * 68 + c] = kv4.w;
      *(float4*)(Vs + c * 68 + d4 * 4) =
          *(const float4*)(vb + (size_t)(kt * 64 + c) * ASH_ + d4 * 4);
    }
    __syncthreads();

    // S = Q K^T  (8x4 per thread)
    float Sa[8][4];
#pragma unroll
    for (int i = 0; i < 8; i++)
#pragma unroll
      for (int j = 0; j < 4; j++) Sa[i][j] = 0.f;
    for (int d = 0; d < 64; d++) {
      float4 a0 = *(const float4*)&Qst[d * 132 + ty * 8];
      float4 a1 = *(const float4*)&Qst[d * 132 + ty * 8 + 4];
      float4 bv = *(const float4*)&Kst[d * 68 + tx * 4];
      float a[8] = {a0.x, a0.y, a0.z, a0.w, a1.x, a1.y, a1.z, a1.w};
      float bb[4] = {bv.x, bv.y, bv.z, bv.w};
#pragma unroll
      for (int i = 0; i < 8; i++)
#pragma unroll
        for (int j = 0; j < 4; j++)
          Sa[i][j] = fmaf(a[i], bb[j], Sa[i][j]);
    }

    // causal mask
#pragma unroll
    for (int i = 0; i < 8; i++) {
      int row = r0 + ty * 8 + i;
#pragma unroll
      for (int j = 0; j < 4; j++) {
        int col = kt * 64 + tx * 4 + j;
        if (col > row) Sa[i][j] = -1e30f;
      }
    }

    // online softmax per row (16 tx lanes share a row group)
#pragma unroll
    for (int i = 0; i < 8; i++) {
      float mx = fmaxf(fmaxf(Sa[i][0], Sa[i][1]), fmaxf(Sa[i][2], Sa[i][3]));
#pragma unroll
      for (int d = 8; d >= 1; d >>= 1)
        mx = fmaxf(mx, __shfl_xor_sync(0xffffffffu, mx, d));
      float mnew = fmaxf(m_run[i], mx);
      float alpha = __expf(m_run[i] - mnew);
      m_run[i] = mnew;
      float rs = 0.f;
#pragma unroll
      for (int j = 0; j < 4; j++) {
        float pv = __expf(Sa[i][j] - mnew);
        Sa[i][j] = pv;
        rs += pv;
      }
#pragma unroll
      for (int d = 8; d >= 1; d >>= 1)
        rs += __shfl_xor_sync(0xffffffffu, rs, d);
      l_run[i] = l_run[i] * alpha + rs;
#pragma unroll
      for (int j = 0; j < 4; j++) Oa[i][j] *= alpha;
    }

    // stash P transposed for the PV mini-GEMM
#pragma unroll
    for (int i = 0; i < 8; i++)
#pragma unroll
      for (int j = 0; j < 4; j++)
        Pst[(tx * 4 + j) * 132 + ty * 8 + i] = Sa[i][j];
    __syncthreads();

    // O += P V
    for (int k = 0; k < 64; k++) {
      float4 p0 = *(const float4*)&Pst[k * 132 + ty * 8];
      float4 p1 = *(const float4*)&Pst[k * 132 + ty * 8 + 4];
      float4 vv = *(const float4*)&Vs[k * 68 + tx * 4];
      float pp[8] = {p0.x, p0.y, p0.z, p0.w, p1.x, p1.y, p1.z, p1.w};
      float vb4[4] = {vv.x, vv.y, vv.z, vv.w};
#pragma unroll
      for (int i = 0; i < 8; i++)
#pragma unroll
        for (int j = 0; j < 4; j++)
          Oa[i][j] = fmaf(pp[i], vb4[j], Oa[i][j]);
    }
  }

  // epilogue: normalize + store [m][h*64+d]
#pragma unroll
  for (int i = 0; i < 8; i++) {
    float inv = 1.f / l_run[i];
    int row = r0 + ty * 8 + i;
    float4 ov = {Oa[i][0] * inv, Oa[i][1] * inv, Oa[i][2] * inv, Oa[i][3] * inv};
    *(float4*)(o + (size_t)(b * S_ + row) * DIM_ + h * 64 + tx * 4) = ov;
  }
}

// ---------------------------------------------------------------------------
extern "C" void kernel_launch(void* const* d_in, const int* in_sizes, int n_in,
                              void* d_out, int out_size) {
  const float* x    = (const float*)d_in[0];
  const float* fc   = (const float*)d_in[1];
  const float* fs   = (const float*)d_in[2];
  const float* wqkv = (const float*)d_in[3];
  const float* wo   = (const float*)d_in[4];
  float* out = (float*)d_out;

  float *qkv_p, *o_p;
  cudaGetSymbolAddress((void**)&qkv_p, g_qkv);
  cudaGetSymbolAddress((void**)&o_p, g_o);

  const int smem_attn = 25600 * sizeof(float);  // 102400 B
  cudaFuncSetAttribute(flash_attn, cudaFuncAttributeMaxDynamicSharedMemorySize,
                       smem_attn);

  // 1) QKV projection: [4096,2048] x [3072,2048]^T -> [4096,3072]
  sgemm_nt<<<dim3(ASH_ / 128, MTOT_ / 128), 256>>>(x, wqkv, qkv_p, ASH_, DIM_);

  // 2) RoPE on q + k
  {
    int total = MTOT_ * 40 * 32;
    rope_kernel<<<(total + 255) / 256, 256>>>(qkv_p, fc, fs);
  }

  // 3) causal GQA flash attention
  flash_attn<<<dim3(S_ / 128, NH_, B_), 256, smem_attn>>>(qkv_p, o_p);

  // 4) output projection: [4096,2048] x [2048,2048]^T -> [4096,2048]
  sgemm_nt<<<dim3(DIM_ / 128, MTOT_ / 128), 256>>>(o_p, wo, out, DIM_, DIM_);
}

// round 10
// speedup vs baseline: 2.1033x; 2.1033x over previous
#include <cuda_runtime.h>
#include <cstdint>
#include <math.h>

#define B_    4
#define S_    1024
#define DIM_  2048
#define NH_   32
#define NKV_  8
#define HD_   64
#define ASH_  3072     // (32 + 2*8) * 64
#define MTOT_ 4096     // B_ * S_
#define KDIM_ 2048

// ---- mma.sync tf32 GEMM tiling ----
#define STAGES   4
#define BM       128
#define BN       128
#define BK       16
#define NIT      (KDIM_ / BK)        // 128
#define LDS_STR  20                  // padded smem stride (floats)
#define A_BYTES  (BM * LDS_STR * 4)  // 10240
#define STG_BYTES (2 * A_BYTES)      // 20480
#define SMEM_TOT (STAGES * STG_BYTES)  // 81920

// Scratch (allocation-free: __device__ globals)
__device__ float g_qkv[MTOT_ * ASH_];    // 48 MB
__device__ float g_o[MTOT_ * DIM_];      // 32 MB (tf32-rounded at store)
__device__ float g_xr[MTOT_ * DIM_];     // 32 MB: tf32-rounded x
__device__ float g_wqkvr[ASH_ * DIM_];   // 24 MB: tf32-rounded wqkv
__device__ float g_wor[DIM_ * DIM_];     // 16 MB: tf32-rounded wo

// ---------------------------------------------------------------------------
// PTX helpers (sm_80-baseline only: cp.async + mma.sync + cvt.rna.tf32)
// ---------------------------------------------------------------------------
__device__ __forceinline__ uint32_t s2u(const void* p) {
  uint32_t a;
  asm("{ .reg .u64 t; cvta.to.shared.u64 t, %1; cvt.u32.u64 %0, t; }"
      : "=r"(a) : "l"(p));
  return a;
}
__device__ __forceinline__ float to_tf32(float x) {
  float y;
  asm("cvt.rna.tf32.f32 %0, %1;" : "=f"(y) : "f"(x));
  return y;
}
__device__ __forceinline__ void cpa16(uint32_t dst, const void* src) {
  asm volatile("cp.async.cg.shared.global [%0], [%1], 16;" :: "r"(dst), "l"(src));
}
__device__ __forceinline__ void cpa_commit() {
  asm volatile("cp.async.commit_group;" ::: "memory");
}
template <int N>
__device__ __forceinline__ void cpa_wait() {
  asm volatile("cp.async.wait_group %0;" :: "n"(N) : "memory");
}
__device__ __forceinline__ void mma_tf32_16x8x8(float* d, const uint32_t* a,
                                                const uint32_t* b) {
  asm volatile(
      "mma.sync.aligned.m16n8k8.row.col.f32.tf32.tf32.f32 "
      "{%0,%1,%2,%3}, {%4,%5,%6,%7}, {%8,%9}, {%0,%1,%2,%3};\n"
      : "+f"(d[0]), "+f"(d[1]), "+f"(d[2]), "+f"(d[3])
      : "r"(a[0]), "r"(a[1]), "r"(a[2]), "r"(a[3]), "r"(b[0]), "r"(b[1]));
}

// ---------------------------------------------------------------------------
// tf32 rounding kernel (unbiased rna rounding before tensor-core consumption)
// ---------------------------------------------------------------------------
__global__ void round_tf32_kernel(const float* __restrict__ src,
                                  float* __restrict__ dst, int n4) {
  int i = blockIdx.x * blockDim.x + threadIdx.x;
  if (i >= n4) return;
  float4 v = ((const float4*)src)[i];
  v.x = to_tf32(v.x); v.y = to_tf32(v.y); v.z = to_tf32(v.z); v.w = to_tf32(v.w);
  ((float4*)dst)[i] = v;
}

// ---------------------------------------------------------------------------
// mma.sync tf32 GEMM (NT): C[m][n] = sum_k A[m][k] * B[n][k]
// 128x128 block, BK=16, 256 threads = 8 warps (2M x 4N), warp tile 64x32.
// 4-stage cp.async pipeline. Grid = (Ntot/128, Mtot/128).
// ---------------------------------------------------------------------------
__global__ __launch_bounds__(256) void gemm_mma(const float* __restrict__ A,
                                                const float* __restrict__ B,
                                                float* __restrict__ C,
                                                int Ntot) {
  extern __shared__ float smf[];
  const uint32_t sb = s2u(smf);
  const int tid = threadIdx.x, wid = tid >> 5, lid = tid & 31;
  const int wm = wid & 1, wn = wid >> 1;     // 2 x 4 warp grid
  const int r = lid >> 2, cc = lid & 3;      // groupID / threadID_in_group
  const int m0 = blockIdx.y * BM, n0 = blockIdx.x * BN;

  const float* Abase = A + (size_t)m0 * KDIM_;
  const float* Bbase = B + (size_t)n0 * KDIM_;

  auto load_tile = [&](int i) {
    uint32_t st = sb + (i % STAGES) * STG_BYTES;
    int k0 = i * BK;
#pragma unroll
    for (int c = 0; c < 2; c++) {     // A: 512 chunks of 16B
      int ch = tid + c * 256;
      int m = ch >> 2, kc = ch & 3;
      cpa16(st + (uint32_t)(m * (LDS_STR * 4) + kc * 16),
            Abase + (size_t)m * KDIM_ + k0 + kc * 4);
    }
#pragma unroll
    for (int c = 0; c < 2; c++) {     // B: 512 chunks of 16B
      int ch = tid + c * 256;
      int n = ch >> 2, kc = ch & 3;
      cpa16(st + A_BYTES + (uint32_t)(n * (LDS_STR * 4) + kc * 16),
            Bbase + (size_t)n * KDIM_ + k0 + kc * 4);
    }
  };

  float acc[4][4][4];
#pragma unroll
  for (int mt = 0; mt < 4; mt++)
#pragma unroll
    for (int nt = 0; nt < 4; nt++)
#pragma unroll
      for (int q = 0; q < 4; q++) acc[mt][nt][q] = 0.f;

  // prologue: fill pipeline
#pragma unroll
  for (int i = 0; i < STAGES; i++) { load_tile(i); cpa_commit(); }

  for (int i = 0; i < NIT; i++) {
    int s = i % STAGES;
    cpa_wait<STAGES - 1>();
    __syncthreads();

    const float* As = smf + s * (STG_BYTES / 4);
    const float* Bs = As + BM * LDS_STR;
#pragma unroll
    for (int ks = 0; ks < 2; ks++) {
      const int k = ks * 8;
      uint32_t af[4][4], bf[4][2];
#pragma unroll
      for (int mt = 0; mt < 4; mt++) {
        const float* ap = As + (wm * 64 + mt * 16 + r) * LDS_STR + k + cc;
        af[mt][0] = __float_as_uint(ap[0]);
        af[mt][1] = __float_as_uint(ap[8 * LDS_STR]);
        af[mt][2] = __float_as_uint(ap[4]);
        af[mt][3] = __float_as_uint(ap[8 * LDS_STR + 4]);
      }
#pragma unroll
      for (int nt = 0; nt < 4; nt++) {
        const float* bp = Bs + (wn * 32 + nt * 8 + r) * LDS_STR + k + cc;
        bf[nt][0] = __float_as_uint(bp[0]);
        bf[nt][1] = __float_as_uint(bp[4]);
      }
#pragma unroll
      for (int mt = 0; mt < 4; mt++)
#pragma unroll
        for (int nt = 0; nt < 4; nt++)
          mma_tf32_16x8x8(acc[mt][nt], af[mt], bf[nt]);
    }
    __syncthreads();   // stage s fully consumed by all warps before refill

    int j = i + STAGES;
    if (j < NIT) load_tile(j);
    cpa_commit();      // exactly one group per iteration
  }

  // epilogue
#pragma unroll
  for (int mt = 0; mt < 4; mt++) {
    int row0 = m0 + wm * 64 + mt * 16 + r;
#pragma unroll
    for (int nt = 0; nt < 4; nt++) {
      int col = n0 + wn * 32 + nt * 8 + cc * 2;
      float2 v01 = {acc[mt][nt][0], acc[mt][nt][1]};
      float2 v23 = {acc[mt][nt][2], acc[mt][nt][3]};
      *(float2*)(C + (size_t)row0 * Ntot + col) = v01;
      *(float2*)(C + (size_t)(row0 + 8) * Ntot + col) = v23;
    }
  }
}

// ---------------------------------------------------------------------------
// RoPE in-place on q (slots 0..3) and k (slot 4) of g_qkv.
// ---------------------------------------------------------------------------
__global__ void rope_kernel(float* __restrict__ qkv,
                            const float* __restrict__ cs,
                            const float* __restrict__ sn) {
  int p = blockIdx.x * blockDim.x + threadIdx.x;
  if (p >= MTOT_ * 40 * 32) return;
  int i = p & 31;
  int hh = (p >> 5) % 40;
  int m = p / (40 * 32);
  int s = m & (S_ - 1);
  int g = hh / 5, j = hh - g * 5;
  size_t base = (size_t)m * ASH_ + g * 384 + j * 64 + 2 * i;
  float2 v = *(float2*)(qkv + base);
  float c = cs[s * 32 + i], si = sn[s * 32 + i];
  float2 o;
  o.x = v.x * c - v.y * si;
  o.y = v.x * si + v.y * c;
  *(float2*)(qkv + base) = o;
}

// ---------------------------------------------------------------------------
// Flash attention (causal, GQA) — scalar fp32; output stored tf32-rounded so
// the tensor-core output projection sees unbiased operands.
// ---------------------------------------------------------------------------
__global__ __launch_bounds__(256) void flash_attn(
    const float* __restrict__ qkv, float* __restrict__ o) {
  extern __shared__ float smf[];
  float* Qst = smf;
  float* Kst = smf + 64 * 132;
  float* Vs  = smf + 64 * 132 + 64 * 68;
  float* Pst = smf + 64 * 132 + 2 * 64 * 68;

  const int qt = blockIdx.x, h = blockIdx.y, b = blockIdx.z;
  const int g = h >> 2;
  const float* qb = qkv + (size_t)b * S_ * ASH_ + g * 384 + (h & 3) * 64;
  const float* kb = qkv + (size_t)b * S_ * ASH_ + g * 384 + 256;
  const float* vb = qkv + (size_t)b * S_ * ASH_ + g * 384 + 320;
  const int tid = threadIdx.x;
  const int ty = tid >> 4, tx = tid & 15;
  const int r0 = qt * 128;

  for (int f = tid; f < 128 * 16; f += 256) {
    int row = f >> 4, d4 = f & 15;
    float4 v = *(const float4*)(qb + (size_t)(r0 + row) * ASH_ + d4 * 4);
    Qst[(d4 * 4 + 0) * 132 + row] = v.x * 0.125f;
    Qst[(d4 * 4 + 1) * 132 + row] = v.y * 0.125f;
    Qst[(d4 * 4 + 2) * 132 + row] = v.z * 0.125f;
    Qst[(d4 * 4 + 3) * 132 + row] = v.w * 0.125f;
  }

  float m_run[8], l_run[8], Oa[8][4];
#pragma unroll
  for (int i = 0; i < 8; i++) {
    m_run[i] = -1e30f;
    l_run[i] = 0.f;
#pragma unroll
    for (int j = 0; j < 4; j++) Oa[i][j] = 0.f;
  }

  const int nkt = 2 * qt + 2;
  for (int kt = 0; kt < nkt; kt++) {
    __syncthreads();
    for (int f = tid; f < 64 * 16; f += 256) {
      int c = f >> 4, d4 = f & 15;
      float4 kv4 = *(const float4*)(kb + (size_t)(kt * 64 + c) * ASH_ + d4 * 4);
      Kst[(d4 * 4 + 0) * 68 + c] = kv4.x;
      Kst[(d4 * 4 + 1) * 68 + c] = kv4.y;
      Kst[(d4 * 4 + 2) * 68 + c] = kv4.z;
      Kst[(d4 * 4 + 3) * 68 + c] = kv4.w;
      *(float4*)(Vs + c * 68 + d4 * 4) =
          *(const float4*)(vb + (size_t)(kt * 64 + c) * ASH_ + d4 * 4);
    }
    __syncthreads();

    float Sa[8][4];
#pragma unroll
    for (int i = 0; i < 8; i++)
#pragma unroll
      for (int j = 0; j < 4; j++) Sa[i][j] = 0.f;
    for (int d = 0; d < 64; d++) {
      float4 a0 = *(const float4*)&Qst[d * 132 + ty * 8];
      float4 a1 = *(const float4*)&Qst[d * 132 + ty * 8 + 4];
      float4 bv = *(const float4*)&Kst[d * 68 + tx * 4];
      float a[8] = {a0.x, a0.y, a0.z, a0.w, a1.x, a1.y, a1.z, a1.w};
      float bb[4] = {bv.x, bv.y, bv.z, bv.w};
#pragma unroll
      for (int i = 0; i < 8; i++)
#pragma unroll
        for (int j = 0; j < 4; j++)
          Sa[i][j] = fmaf(a[i], bb[j], Sa[i][j]);
    }

#pragma unroll
    for (int i = 0; i < 8; i++) {
      int row = r0 + ty * 8 + i;
#pragma unroll
      for (int j = 0; j < 4; j++) {
        int col = kt * 64 + tx * 4 + j;
        if (col > row) Sa[i][j] = -1e30f;
      }
    }

#pragma unroll
    for (int i = 0; i < 8; i++) {
      float mx = fmaxf(fmaxf(Sa[i][0], Sa[i][1]), fmaxf(Sa[i][2], Sa[i][3]));
#pragma unroll
      for (int d = 8; d >= 1; d >>= 1)
        mx = fmaxf(mx, __shfl_xor_sync(0xffffffffu, mx, d));
      float mnew = fmaxf(m_run[i], mx);
      float alpha = __expf(m_run[i] - mnew);
      m_run[i] = mnew;
      float rs = 0.f;
#pragma unroll
      for (int j = 0; j < 4; j++) {
        float pv = __expf(Sa[i][j] - mnew);
        Sa[i][j] = pv;
        rs += pv;
      }
#pragma unroll
      for (int d = 8; d >= 1; d >>= 1)
        rs += __shfl_xor_sync(0xffffffffu, rs, d);
      l_run[i] = l_run[i] * alpha + rs;
#pragma unroll
      for (int j = 0; j < 4; j++) Oa[i][j] *= alpha;
    }

#pragma unroll
    for (int i = 0; i < 8; i++)
#pragma unroll
      for (int j = 0; j < 4; j++)
        Pst[(tx * 4 + j) * 132 + ty * 8 + i] = Sa[i][j];
    __syncthreads();

    for (int k = 0; k < 64; k++) {
      float4 p0 = *(const float4*)&Pst[k * 132 + ty * 8];
      float4 p1 = *(const float4*)&Pst[k * 132 + ty * 8 + 4];
      float4 vv = *(const float4*)&Vs[k * 68 + tx * 4];
      float pp[8] = {p0.x, p0.y, p0.z, p0.w, p1.x, p1.y, p1.z, p1.w};
      float vb4[4] = {vv.x, vv.y, vv.z, vv.w};
#pragma unroll
      for (int i = 0; i < 8; i++)
#pragma unroll
        for (int j = 0; j < 4; j++)
          Oa[i][j] = fmaf(pp[i], vb4[j], Oa[i][j]);
    }
  }

#pragma unroll
  for (int i = 0; i < 8; i++) {
    float inv = 1.f / l_run[i];
    int row = r0 + ty * 8 + i;
    float4 ov = {to_tf32(Oa[i][0] * inv), to_tf32(Oa[i][1] * inv),
                 to_tf32(Oa[i][2] * inv), to_tf32(Oa[i][3] * inv)};
    *(float4*)(o + (size_t)(b * S_ + row) * DIM_ + h * 64 + tx * 4) = ov;
  }
}

// ---------------------------------------------------------------------------
extern "C" void kernel_launch(void* const* d_in, const int* in_sizes, int n_in,
                              void* d_out, int out_size) {
  const float* x    = (const float*)d_in[0];
  const float* fc   = (const float*)d_in[1];
  const float* fs   = (const float*)d_in[2];
  const float* wqkv = (const float*)d_in[3];
  const float* wo   = (const float*)d_in[4];
  float* out = (float*)d_out;

  float *qkv_p, *o_p, *xr_p, *wqkvr_p, *wor_p;
  cudaGetSymbolAddress((void**)&qkv_p, g_qkv);
  cudaGetSymbolAddress((void**)&o_p, g_o);
  cudaGetSymbolAddress((void**)&xr_p, g_xr);
  cudaGetSymbolAddress((void**)&wqkvr_p, g_wqkvr);
  cudaGetSymbolAddress((void**)&wor_p, g_wor);

  const int smem_attn = 25600 * sizeof(float);  // 102400 B
  cudaFuncSetAttribute(flash_attn, cudaFuncAttributeMaxDynamicSharedMemorySize,
                       smem_attn);
  cudaFuncSetAttribute(gemm_mma, cudaFuncAttributeMaxDynamicSharedMemorySize,
                       SMEM_TOT);

  // 0) unbiased tf32 rounding of GEMM operands
  {
    int n4 = MTOT_ * DIM_ / 4;
    round_tf32_kernel<<<(n4 + 255) / 256, 256>>>(x, xr_p, n4);
    n4 = ASH_ * DIM_ / 4;
    round_tf32_kernel<<<(n4 + 255) / 256, 256>>>(wqkv, wqkvr_p, n4);
    n4 = DIM_ * DIM_ / 4;
    round_tf32_kernel<<<(n4 + 255) / 256, 256>>>(wo, wor_p, n4);
  }

  // 1) QKV projection (mma.sync tf32): [4096,2048] x [3072,2048]^T
  gemm_mma<<<dim3(ASH_ / BN, MTOT_ / BM), 256, SMEM_TOT>>>(xr_p, wqkvr_p,
                                                           qkv_p, ASH_);

  // 2) RoPE
  {
    int total = MTOT_ * 40 * 32;
    rope_kernel<<<(total + 255) / 256, 256>>>(qkv_p, fc, fs);
  }

  // 3) causal GQA flash attention (fp32 scalar)
  flash_attn<<<dim3(S_ / 128, NH_, B_), 256, smem_attn>>>(qkv_p, o_p);

  // 4) output projection (mma.sync tf32): [4096,2048] x [2048,2048]^T
  gemm_mma<<<dim3(DIM_ / BN, MTOT_ / BM), 256, SMEM_TOT>>>(o_p, wor_p, out,
                                                           DIM_);
}

// round 12
// speedup vs baseline: 3.0093x; 1.4308x over previous
#include <cuda_runtime.h>
#include <cstdint>
#include <math.h>

#define B_    4
#define S_    1024
#define DIM_  2048
#define NH_   32
#define NKV_  8
#define HD_   64
#define ASH_  3072     // (32 + 2*8) * 64
#define MTOT_ 4096     // B_ * S_
#define KDIM_ 2048

// ---- mma.sync tf32 GEMM tiling ----
#define STAGES   4
#define BM       128
#define BN       128
#define BK       16
#define NIT      (KDIM_ / BK)        // 128
#define LDS_STR  20                  // padded smem stride (floats)
#define A_BYTES  (BM * LDS_STR * 4)  // 10240
#define STG_BYTES (2 * A_BYTES)      // 20480
#define SMEM_TOT (STAGES * STG_BYTES)  // 81920

// ---- flash attention smem layout (floats) ----
#define KPAD  68
#define VPAD  72
#define KS_F  (2 * 64 * KPAD)        // 8704
#define VS_F  (2 * 64 * VPAD)        // 9216
#define PS_F  (128 * KPAD)           // 8704
#define ATTN_SMEM_B ((KS_F + VS_F + PS_F) * 4)  // 106496

// Scratch (allocation-free: __device__ globals)
__device__ float g_qkv[MTOT_ * ASH_];    // 48 MB
__device__ float g_o[MTOT_ * DIM_];      // 32 MB

// ---------------------------------------------------------------------------
// PTX helpers (sm_80-baseline only: cp.async + mma.sync + cvt.rna.tf32)
// ---------------------------------------------------------------------------
__device__ __forceinline__ uint32_t s2u(const void* p) {
  uint32_t a;
  asm("{ .reg .u64 t; cvta.to.shared.u64 t, %1; cvt.u32.u64 %0, t; }"
      : "=r"(a) : "l"(p));
  return a;
}
__device__ __forceinline__ float to_tf32(float x) {
  float y;
  asm("cvt.rna.tf32.f32 %0, %1;" : "=f"(y) : "f"(x));
  return y;
}
__device__ __forceinline__ uint32_t tf32u(float x) {
  return __float_as_uint(to_tf32(x));
}
__device__ __forceinline__ void cpa16(uint32_t dst, const void* src) {
  asm volatile("cp.async.cg.shared.global [%0], [%1], 16;" :: "r"(dst), "l"(src));
}
__device__ __forceinline__ void cpa_commit() {
  asm volatile("cp.async.commit_group;" ::: "memory");
}
template <int N>
__device__ __forceinline__ void cpa_wait() {
  asm volatile("cp.async.wait_group %0;" :: "n"(N) : "memory");
}
__device__ __forceinline__ void mma_tf32_16x8x8(float* d, const uint32_t* a,
                                                const uint32_t* b) {
  asm volatile(
      "mma.sync.aligned.m16n8k8.row.col.f32.tf32.tf32.f32 "
      "{%0,%1,%2,%3}, {%4,%5,%6,%7}, {%8,%9}, {%0,%1,%2,%3};\n"
      : "+f"(d[0]), "+f"(d[1]), "+f"(d[2]), "+f"(d[3])
      : "r"(a[0]), "r"(a[1]), "r"(a[2]), "r"(a[3]), "r"(b[0]), "r"(b[1]));
}

// ---------------------------------------------------------------------------
// mma.sync tf32 GEMM (NT): C[m][n] = sum_k A[m][k] * B[n][k]
// 128x128 block, BK=16, 256 threads = 8 warps (2M x 4N), warp tile 64x32.
// 4-stage cp.async pipeline; tf32 rna rounding fused into fragment loads.
// ---------------------------------------------------------------------------
__global__ __launch_bounds__(256) void gemm_mma(const float* __restrict__ A,
                                                const float* __restrict__ B,
                                                float* __restrict__ C,
                                                int Ntot) {
  extern __shared__ float smf[];
  const uint32_t sb = s2u(smf);
  const int tid = threadIdx.x, wid = tid >> 5, lid = tid & 31;
  const int wm = wid & 1, wn = wid >> 1;     // 2 x 4 warp grid
  const int r = lid >> 2, cc = lid & 3;
  const int m0 = blockIdx.y * BM, n0 = blockIdx.x * BN;

  const float* Abase = A + (size_t)m0 * KDIM_;
  const float* Bbase = B + (size_t)n0 * KDIM_;

  auto load_tile = [&](int i) {
    uint32_t st = sb + (i % STAGES) * STG_BYTES;
    int k0 = i * BK;
#pragma unroll
    for (int c = 0; c < 2; c++) {     // A: 512 chunks of 16B
      int ch = tid + c * 256;
      int m = ch >> 2, kc = ch & 3;
      cpa16(st + (uint32_t)(m * (LDS_STR * 4) + kc * 16),
            Abase + (size_t)m * KDIM_ + k0 + kc * 4);
    }
#pragma unroll
    for (int c = 0; c < 2; c++) {     // B: 512 chunks of 16B
      int ch = tid + c * 256;
      int n = ch >> 2, kc = ch & 3;
      cpa16(st + A_BYTES + (uint32_t)(n * (LDS_STR * 4) + kc * 16),
            Bbase + (size_t)n * KDIM_ + k0 + kc * 4);
    }
  };

  float acc[4][4][4];
#pragma unroll
  for (int mt = 0; mt < 4; mt++)
#pragma unroll
    for (int nt = 0; nt < 4; nt++)
#pragma unroll
      for (int q = 0; q < 4; q++) acc[mt][nt][q] = 0.f;

#pragma unroll
  for (int i = 0; i < STAGES; i++) { load_tile(i); cpa_commit(); }

  for (int i = 0; i < NIT; i++) {
    int s = i % STAGES;
    cpa_wait<STAGES - 1>();
    __syncthreads();

    const float* As = smf + s * (STG_BYTES / 4);
    const float* Bs = As + BM * LDS_STR;
#pragma unroll
    for (int ks = 0; ks < 2; ks++) {
      const int k = ks * 8;
      uint32_t af[4][4], bf[4][2];
#pragma unroll
      for (int mt = 0; mt < 4; mt++) {
        const float* ap = As + (wm * 64 + mt * 16 + r) * LDS_STR + k + cc;
        af[mt][0] = tf32u(ap[0]);
        af[mt][1] = tf32u(ap[8 * LDS_STR]);
        af[mt][2] = tf32u(ap[4]);
        af[mt][3] = tf32u(ap[8 * LDS_STR + 4]);
      }
#pragma unroll
      for (int nt = 0; nt < 4; nt++) {
        const float* bp = Bs + (wn * 32 + nt * 8 + r) * LDS_STR + k + cc;
        bf[nt][0] = tf32u(bp[0]);
        bf[nt][1] = tf32u(bp[4]);
      }
#pragma unroll
      for (int mt = 0; mt < 4; mt++)
#pragma unroll
        for (int nt = 0; nt < 4; nt++)
          mma_tf32_16x8x8(acc[mt][nt], af[mt], bf[nt]);
    }
    __syncthreads();

    int j = i + STAGES;
    if (j < NIT) load_tile(j);
    cpa_commit();
  }

#pragma unroll
  for (int mt = 0; mt < 4; mt++) {
    int row0 = m0 + wm * 64 + mt * 16 + r;
#pragma unroll
    for (int nt = 0; nt < 4; nt++) {
      int col = n0 + wn * 32 + nt * 8 + cc * 2;
      float2 v01 = {acc[mt][nt][0], acc[mt][nt][1]};
      float2 v23 = {acc[mt][nt][2], acc[mt][nt][3]};
      *(float2*)(C + (size_t)row0 * Ntot + col) = v01;
      *(float2*)(C + (size_t)(row0 + 8) * Ntot + col) = v23;
    }
  }
}

// ---------------------------------------------------------------------------
// RoPE in-place on q (slots 0..3) and k (slot 4) of g_qkv.
// ---------------------------------------------------------------------------
__global__ void rope_kernel(float* __restrict__ qkv,
                            const float* __restrict__ cs,
                            const float* __restrict__ sn) {
  int p = blockIdx.x * blockDim.x + threadIdx.x;
  if (p >= MTOT_ * 40 * 32) return;
  int i = p & 31;
  int hh = (p >> 5) % 40;
  int m = p / (40 * 32);
  int s = m & (S_ - 1);
  int g = hh / 5, j = hh - g * 5;
  size_t base = (size_t)m * ASH_ + g * 384 + j * 64 + 2 * i;
  float2 v = *(float2*)(qkv + base);
  float c = cs[s * 32 + i], si = sn[s * 32 + i];
  float2 o;
  o.x = v.x * c - v.y * si;
  o.y = v.x * si + v.y * c;
  *(float2*)(qkv + base) = o;
}

// ---------------------------------------------------------------------------
// Tensor-core flash attention (causal, GQA), tf32 mma.sync.
// Block = 128 q-rows x head x batch. 256 threads = 8 warps x 16 rows.
// QK^T: A=Q frags (regs), B=K from smem (K-major, pad 68, conflict-free).
// PV:   A=P via per-warp smem relay (pad 68), B=V from natural K-major smem
//       with transposed fragment indexing (pad 72 -> conflict-free).
// K/V double-buffered cp.async.
// ---------------------------------------------------------------------------
__global__ __launch_bounds__(256) void flash_mma(const float* __restrict__ qkv,
                                                 float* __restrict__ o) {
  extern __shared__ float smf[];
  float* Ksm = smf;                 // [2][64][KPAD]
  float* Vsm = smf + KS_F;          // [2][64][VPAD]
  float* Psm = smf + KS_F + VS_F;   // [128][KPAD]
  const uint32_t sb = s2u(smf);
  const uint32_t ks_b = sb;
  const uint32_t vs_b = sb + KS_F * 4;

  const int qt = blockIdx.x, h = blockIdx.y, b = blockIdx.z;
  const int g = h >> 2;
  const float* qb = qkv + (size_t)b * S_ * ASH_ + g * 384 + (h & 3) * 64;
  const float* kb = qkv + (size_t)b * S_ * ASH_ + g * 384 + 256;
  const float* vb = qkv + (size_t)b * S_ * ASH_ + g * 384 + 320;
  const int tid = threadIdx.x, wid = tid >> 5, lid = tid & 31;
  const int r = lid >> 2, cc = lid & 3;
  const int r0 = qt * 128;
  const int wrow = wid * 16;

  auto load_kv = [&](int kt, int st) {
#pragma unroll
    for (int c = 0; c < 4; c++) {
      int ch = tid + c * 256;
      int key = ch >> 4, d4 = ch & 15;
      const float* src = kb + (size_t)(kt * 64 + key) * ASH_ + d4 * 4;
      cpa16(ks_b + (uint32_t)(st * 64 * KPAD * 4 + key * (KPAD * 4) + d4 * 16),
            src);
      cpa16(vs_b + (uint32_t)(st * 64 * VPAD * 4 + key * (VPAD * 4) + d4 * 16),
            src + 64);  // vb = kb + 64
    }
  };

  // Q fragments: 16 rows x 64 d per warp, pre-scaled + tf32-rounded.
  uint32_t qf[8][4];
  {
    const float* q0 = qb + (size_t)(r0 + wrow + r) * ASH_;
    const float* q1 = q0 + 8 * ASH_;
#pragma unroll
    for (int ks = 0; ks < 8; ks++) {
      qf[ks][0] = __float_as_uint(to_tf32(0.125f * __ldg(q0 + ks * 8 + cc)));
      qf[ks][1] = __float_as_uint(to_tf32(0.125f * __ldg(q1 + ks * 8 + cc)));
      qf[ks][2] = __float_as_uint(to_tf32(0.125f * __ldg(q0 + ks * 8 + cc + 4)));
      qf[ks][3] = __float_as_uint(to_tf32(0.125f * __ldg(q1 + ks * 8 + cc + 4)));
    }
  }

  float m0r = -1e30f, m1r = -1e30f, l0 = 0.f, l1 = 0.f;
  float Oa[8][4];
#pragma unroll
  for (int nt = 0; nt < 8; nt++)
#pragma unroll
    for (int q = 0; q < 4; q++) Oa[nt][q] = 0.f;

  const int nkt = 2 * qt + 2;
  load_kv(0, 0);
  cpa_commit();

  for (int kt = 0; kt < nkt; kt++) {
    const int st = kt & 1;
    if (kt + 1 < nkt) {
      load_kv(kt + 1, st ^ 1);
      cpa_commit();
      cpa_wait<1>();
    } else {
      cpa_wait<0>();
    }
    __syncthreads();

    const float* Kt = Ksm + st * 64 * KPAD;
    const float* Vt = Vsm + st * 64 * VPAD;

    // S = Q K^T
    float Sa[8][4];
#pragma unroll
    for (int nt = 0; nt < 8; nt++)
#pragma unroll
      for (int q = 0; q < 4; q++) Sa[nt][q] = 0.f;
#pragma unroll
    for (int ks = 0; ks < 8; ks++) {
      uint32_t bf[8][2];
#pragma unroll
      for (int nt = 0; nt < 8; nt++) {
        const float* kp = Kt + (nt * 8 + r) * KPAD + ks * 8 + cc;
        bf[nt][0] = tf32u(kp[0]);
        bf[nt][1] = tf32u(kp[4]);
      }
#pragma unroll
      for (int nt = 0; nt < 8; nt++)
        mma_tf32_16x8x8(Sa[nt], qf[ks], bf[nt]);
    }

    // causal mask (only diagonal-crossing tiles)
    if (kt >= 2 * qt) {
      const int row_a = r0 + wrow + r, row_b = row_a + 8;
#pragma unroll
      for (int nt = 0; nt < 8; nt++) {
        int col = kt * 64 + nt * 8 + 2 * cc;
        if (col > row_a) Sa[nt][0] = -1e30f;
        if (col + 1 > row_a) Sa[nt][1] = -1e30f;
        if (col > row_b) Sa[nt][2] = -1e30f;
        if (col + 1 > row_b) Sa[nt][3] = -1e30f;
      }
    }

    // online softmax: rows r (regs 0,1) and r+8 (regs 2,3); 4 lanes/row.
    float mx0 = -1e30f, mx1 = -1e30f;
#pragma unroll
    for (int nt = 0; nt < 8; nt++) {
      mx0 = fmaxf(mx0, fmaxf(Sa[nt][0], Sa[nt][1]));
      mx1 = fmaxf(mx1, fmaxf(Sa[nt][2], Sa[nt][3]));
    }
#pragma unroll
    for (int d = 1; d <= 2; d <<= 1) {
      mx0 = fmaxf(mx0, __shfl_xor_sync(0xffffffffu, mx0, d));
      mx1 = fmaxf(mx1, __shfl_xor_sync(0xffffffffu, mx1, d));
    }
    float mn0 = fmaxf(m0r, mx0), mn1 = fmaxf(m1r, mx1);
    float al0 = __expf(m0r - mn0), al1 = __expf(m1r - mn1);
    m0r = mn0; m1r = mn1;
    float s0 = 0.f, s1 = 0.f;
#pragma unroll
    for (int nt = 0; nt < 8; nt++) {
      Sa[nt][0] = __expf(Sa[nt][0] - mn0); s0 += Sa[nt][0];
      Sa[nt][1] = __expf(Sa[nt][1] - mn0); s0 += Sa[nt][1];
      Sa[nt][2] = __expf(Sa[nt][2] - mn1); s1 += Sa[nt][2];
      Sa[nt][3] = __expf(Sa[nt][3] - mn1); s1 += Sa[nt][3];
    }
#pragma unroll
    for (int d = 1; d <= 2; d <<= 1) {
      s0 += __shfl_xor_sync(0xffffffffu, s0, d);
      s1 += __shfl_xor_sync(0xffffffffu, s1, d);
    }
    l0 = l0 * al0 + s0;
    l1 = l1 * al1 + s1;
#pragma unroll
    for (int nt = 0; nt < 8; nt++) {
      Oa[nt][0] *= al0; Oa[nt][1] *= al0;
      Oa[nt][2] *= al1; Oa[nt][3] *= al1;
    }

    // P -> per-warp smem relay (tf32-rounded)
    {
      float* pr = Psm + (wrow + r) * KPAD;
#pragma unroll
      for (int nt = 0; nt < 8; nt++) {
        float2 p01 = {to_tf32(Sa[nt][0]), to_tf32(Sa[nt][1])};
        float2 p23 = {to_tf32(Sa[nt][2]), to_tf32(Sa[nt][3])};
        *(float2*)(pr + nt * 8 + 2 * cc) = p01;
        *(float2*)(pr + 8 * KPAD + nt * 8 + 2 * cc) = p23;
      }
    }
    __syncwarp();

    // O += P V
#pragma unroll
    for (int ks = 0; ks < 8; ks++) {
      uint32_t pf[4];
      const float* pp = Psm + (wrow + r) * KPAD + ks * 8 + cc;
      pf[0] = __float_as_uint(pp[0]);
      pf[1] = __float_as_uint(pp[8 * KPAD]);
      pf[2] = __float_as_uint(pp[4]);
      pf[3] = __float_as_uint(pp[8 * KPAD + 4]);
      uint32_t vf[8][2];
#pragma unroll
      for (int nt = 0; nt < 8; nt++) {
        const float* vp = Vt + (ks * 8 + cc) * VPAD + nt * 8 + r;
        vf[nt][0] = tf32u(vp[0]);
        vf[nt][1] = tf32u(vp[4 * VPAD]);
      }
#pragma unroll
      for (int nt = 0; nt < 8; nt++)
        mma_tf32_16x8x8(Oa[nt], pf, vf[nt]);
    }
    __syncthreads();   // all warps done with stage st before it is refilled
  }

  // epilogue: normalize + store [m][h*64+d]
  const float inv0 = 1.f / l0, inv1 = 1.f / l1;
  float* ob = o + (size_t)(b * S_ + r0 + wrow + r) * DIM_ + h * 64;
#pragma unroll
  for (int nt = 0; nt < 8; nt++) {
    float2 v01 = {Oa[nt][0] * inv0, Oa[nt][1] * inv0};
    float2 v23 = {Oa[nt][2] * inv1, Oa[nt][3] * inv1};
    *(float2*)(ob + nt * 8 + 2 * cc) = v01;
    *(float2*)(ob + 8 * DIM_ + nt * 8 + 2 * cc) = v23;
  }
}

// ---------------------------------------------------------------------------
extern "C" void kernel_launch(void* const* d_in, const int* in_sizes, int n_in,
                              void* d_out, int out_size) {
  const float* x    = (const float*)d_in[0];
  const float* fc   = (const float*)d_in[1];
  const float* fs   = (const float*)d_in[2];
  const float* wqkv = (const float*)d_in[3];
  const float* wo   = (const float*)d_in[4];
  float* out = (float*)d_out;

  float *qkv_p, *o_p;
  cudaGetSymbolAddress((void**)&qkv_p, g_qkv);
  cudaGetSymbolAddress((void**)&o_p, g_o);

  cudaFuncSetAttribute(gemm_mma, cudaFuncAttributeMaxDynamicSharedMemorySize,
                       SMEM_TOT);
  cudaFuncSetAttribute(flash_mma, cudaFuncAttributeMaxDynamicSharedMemorySize,
                       ATTN_SMEM_B);

  // 1) QKV projection (mma.sync tf32, rounding fused in fragment loads)
  gemm_mma<<<dim3(ASH_ / BN, MTOT_ / BM), 256, SMEM_TOT>>>(x, wqkv, qkv_p,
                                                           ASH_);

  // 2) RoPE
  {
    int total = MTOT_ * 40 * 32;
    rope_kernel<<<(total + 255) / 256, 256>>>(qkv_p, fc, fs);
  }

  // 3) causal GQA flash attention (mma.sync tf32)
  flash_mma<<<dim3(S_ / 128, NH_, B_), 256, ATTN_SMEM_B>>>(qkv_p, o_p);

  // 4) output projection (mma.sync tf32)
  gemm_mma<<<dim3(DIM_ / BN, MTOT_ / BM), 256, SMEM_TOT>>>(o_p, wo, out,
                                                           DIM_);
}

// round 13
// speedup vs baseline: 3.4022x; 1.1306x over previous
#include <cuda_runtime.h>
#include <cstdint>
#include <math.h>

#define B_    4
#define S_    1024
#define DIM_  2048
#define NH_   32
#define NKV_  8
#define HD_   64
#define ASH_  3072     // (32 + 2*8) * 64
#define MTOT_ 4096     // B_ * S_
#define KDIM_ 2048

// ---- mma.sync tf32 GEMM tiling ----
#define STAGES   4
#define BM       128
#define BN       128
#define BK       16
#define NIT      (KDIM_ / BK)        // 128
#define LDS_STR  24                  // padded smem stride (floats)
#define A_BYTES  (BM * LDS_STR * 4)  // 12288
#define STG_BYTES (2 * A_BYTES)      // 24576
#define SMEM_TOT (STAGES * STG_BYTES)  // 98304

// ---- flash attention smem layout (floats) ----
#define KPAD  68
#define VPAD  72
#define KS_F  (2 * 64 * KPAD)        // 8704
#define VS_F  (2 * 64 * VPAD)        // 9216
#define PS_F  (128 * KPAD)           // 8704
#define ATTN_SMEM_B ((KS_F + VS_F + PS_F) * 4)  // 106496

// Scratch (allocation-free: __device__ globals)
__device__ float g_qkv[MTOT_ * ASH_];    // 48 MB (q/k/v tf32-rounded by rope)
__device__ float g_o[MTOT_ * DIM_];      // 32 MB (tf32-rounded + k-permuted)
__device__ float g_xr[MTOT_ * DIM_];     // 32 MB: rounded+permuted x
__device__ float g_wqkvr[ASH_ * DIM_];   // 24 MB: rounded+permuted wqkv
__device__ float g_wor[DIM_ * DIM_];     // 16 MB: rounded+permuted wo

// ---------------------------------------------------------------------------
// PTX helpers (sm_80-baseline only: cp.async + mma.sync + cvt.rna.tf32)
// ---------------------------------------------------------------------------
__device__ __forceinline__ uint32_t s2u(const void* p) {
  uint32_t a;
  asm("{ .reg .u64 t; cvta.to.shared.u64 t, %1; cvt.u32.u64 %0, t; }"
      : "=r"(a) : "l"(p));
  return a;
}
__device__ __forceinline__ float to_tf32(float x) {
  float y;
  asm("cvt.rna.tf32.f32 %0, %1;" : "=f"(y) : "f"(x));
  return y;
}
__device__ __forceinline__ void cpa16(uint32_t dst, const void* src) {
  asm volatile("cp.async.cg.shared.global [%0], [%1], 16;" :: "r"(dst), "l"(src));
}
__device__ __forceinline__ void cpa_commit() {
  asm volatile("cp.async.commit_group;" ::: "memory");
}
template <int N>
__device__ __forceinline__ void cpa_wait() {
  asm volatile("cp.async.wait_group %0;" :: "n"(N) : "memory");
}
__device__ __forceinline__ void mma_tf32_16x8x8(float* d, const uint32_t* a,
                                                const uint32_t* b) {
  asm volatile(
      "mma.sync.aligned.m16n8k8.row.col.f32.tf32.tf32.f32 "
      "{%0,%1,%2,%3}, {%4,%5,%6,%7}, {%8,%9}, {%0,%1,%2,%3};\n"
      : "+f"(d[0]), "+f"(d[1]), "+f"(d[2]), "+f"(d[3])
      : "r"(a[0]), "r"(a[1]), "r"(a[2]), "r"(a[3]), "r"(b[0]), "r"(b[1]));
}

// ---------------------------------------------------------------------------
// Round to tf32 (rna) and permute each k-8-group to [k0,k4,k1,k5,k2,k6,k3,k7]
// so mma fragment pairs (cc, cc+4) are contiguous in memory.
// ---------------------------------------------------------------------------
__global__ void roundperm_kernel(const float* __restrict__ src,
                                 float* __restrict__ dst, int n8) {
  int i = blockIdx.x * blockDim.x + threadIdx.x;
  if (i >= n8) return;
  const float4* s = (const float4*)src + (size_t)i * 2;
  float4 a = s[0], b = s[1];
  float4 c0 = {to_tf32(a.x), to_tf32(b.x), to_tf32(a.y), to_tf32(b.y)};
  float4 c1 = {to_tf32(a.z), to_tf32(b.z), to_tf32(a.w), to_tf32(b.w)};
  float4* d = (float4*)dst + (size_t)i * 2;
  d[0] = c0;
  d[1] = c1;
}

// ---------------------------------------------------------------------------
// mma.sync tf32 GEMM (NT): C[m][n] = sum_k A[m][k] * B[n][k]
// A and B are pre-rounded + k-permuted. 128x128 block, BK=16, 256 threads =
// 8 warps (2M x 4N), warp tile 64x32. All fragment loads are LDS.64,
// conflict-free (stride 24). 4-stage cp.async, 1 syncthreads per k-iter.
// ---------------------------------------------------------------------------
__global__ __launch_bounds__(256) void gemm_mma(const float* __restrict__ A,
                                                const float* __restrict__ B,
                                                float* __restrict__ C,
                                                int Ntot) {
  extern __shared__ float smf[];
  const uint32_t sb = s2u(smf);
  const int tid = threadIdx.x, wid = tid >> 5, lid = tid & 31;
  const int wm = wid & 1, wn = wid >> 1;     // 2 x 4 warp grid
  const int r = lid >> 2, cc = lid & 3;
  const int m0 = blockIdx.y * BM, n0 = blockIdx.x * BN;

  const float* Abase = A + (size_t)m0 * KDIM_;
  const float* Bbase = B + (size_t)n0 * KDIM_;

  auto load_tile = [&](int i) {
    uint32_t st = sb + (i % STAGES) * STG_BYTES;
    int k0 = i * BK;
#pragma unroll
    for (int c = 0; c < 2; c++) {     // A: 512 chunks of 16B
      int ch = tid + c * 256;
      int m = ch >> 2, kc = ch & 3;
      cpa16(st + (uint32_t)(m * (LDS_STR * 4) + kc * 16),
            Abase + (size_t)m * KDIM_ + k0 + kc * 4);
    }
#pragma unroll
    for (int c = 0; c < 2; c++) {     // B: 512 chunks of 16B
      int ch = tid + c * 256;
      int n = ch >> 2, kc = ch & 3;
      cpa16(st + A_BYTES + (uint32_t)(n * (LDS_STR * 4) + kc * 16),
            Bbase + (size_t)n * KDIM_ + k0 + kc * 4);
    }
  };

  float acc[4][4][4];
#pragma unroll
  for (int mt = 0; mt < 4; mt++)
#pragma unroll
    for (int nt = 0; nt < 4; nt++)
#pragma unroll
      for (int q = 0; q < 4; q++) acc[mt][nt][q] = 0.f;

  // prologue: 3 tiles in flight
#pragma unroll
  for (int i = 0; i < STAGES - 1; i++) { load_tile(i); cpa_commit(); }

  for (int i = 0; i < NIT; i++) {
    int s = i % STAGES;
    cpa_wait<STAGES - 2>();
    __syncthreads();   // all warps done with slot (i-1)%STAGES, tile i ready

    int j = i + STAGES - 1;
    if (j < NIT) { load_tile(j); cpa_commit(); }

    const float* As = smf + s * (STG_BYTES / 4);
    const float* Bs = As + BM * LDS_STR;
#pragma unroll
    for (int ks = 0; ks < 2; ks++) {
      const int k = ks * 8;
      uint32_t af[4][4], bf[4][2];
#pragma unroll
      for (int mt = 0; mt < 4; mt++) {
        const float2 v0 =
            *(const float2*)(As + (wm * 64 + mt * 16 + r) * LDS_STR + k + 2 * cc);
        const float2 v1 =
            *(const float2*)(As + (wm * 64 + mt * 16 + r + 8) * LDS_STR + k + 2 * cc);
        af[mt][0] = __float_as_uint(v0.x);
        af[mt][1] = __float_as_uint(v1.x);
        af[mt][2] = __float_as_uint(v0.y);
        af[mt][3] = __float_as_uint(v1.y);
      }
#pragma unroll
      for (int nt = 0; nt < 4; nt++) {
        const float2 bv =
            *(const float2*)(Bs + (wn * 32 + nt * 8 + r) * LDS_STR + k + 2 * cc);
        bf[nt][0] = __float_as_uint(bv.x);
        bf[nt][1] = __float_as_uint(bv.y);
      }
#pragma unroll
      for (int mt = 0; mt < 4; mt++)
#pragma unroll
        for (int nt = 0; nt < 4; nt++)
          mma_tf32_16x8x8(acc[mt][nt], af[mt], bf[nt]);
    }
  }

  // epilogue
#pragma unroll
  for (int mt = 0; mt < 4; mt++) {
    int row0 = m0 + wm * 64 + mt * 16 + r;
#pragma unroll
    for (int nt = 0; nt < 4; nt++) {
      int col = n0 + wn * 32 + nt * 8 + cc * 2;
      float2 v01 = {acc[mt][nt][0], acc[mt][nt][1]};
      float2 v23 = {acc[mt][nt][2], acc[mt][nt][3]};
      *(float2*)(C + (size_t)row0 * Ntot + col) = v01;
      *(float2*)(C + (size_t)(row0 + 8) * Ntot + col) = v23;
    }
  }
}

// ---------------------------------------------------------------------------
// RoPE in-place on q (slots 0..3) and k (slot 4); v (slot 5) pass-through.
// ALL outputs tf32-rounded so flash_mma needs no cvt on Q/K/V.
// ---------------------------------------------------------------------------
__global__ void rope_kernel(float* __restrict__ qkv,
                            const float* __restrict__ cs,
                            const float* __restrict__ sn) {
  int p = blockIdx.x * blockDim.x + threadIdx.x;
  if (p >= MTOT_ * 48 * 32) return;
  int i = p & 31;
  int hh = (p >> 5) % 48;
  int m = p / (48 * 32);
  int s = m & (S_ - 1);
  int g = hh / 6, j = hh - g * 6;    // j: 0..3 q slots, 4 k, 5 v
  size_t base = (size_t)m * ASH_ + g * 384 + j * 64 + 2 * i;
  float2 v = *(float2*)(qkv + base);
  float2 o;
  if (j < 5) {
    float c = cs[s * 32 + i], si = sn[s * 32 + i];
    o.x = to_tf32(v.x * c - v.y * si);
    o.y = to_tf32(v.x * si + v.y * c);
  } else {
    o.x = to_tf32(v.x);
    o.y = to_tf32(v.y);
  }
  *(float2*)(qkv + base) = o;
}

// ---------------------------------------------------------------------------
// Tensor-core flash attention (causal, GQA), tf32 mma.sync.
// Q/K/V pre-rounded by rope => no cvt in the mainloop. Output written
// tf32-rounded AND k-permuted so it feeds gemm_mma directly as operand A.
// ---------------------------------------------------------------------------
__global__ __launch_bounds__(256) void flash_mma(const float* __restrict__ qkv,
                                                 float* __restrict__ o) {
  extern __shared__ float smf[];
  float* Ksm = smf;                 // [2][64][KPAD]
  float* Vsm = smf + KS_F;          // [2][64][VPAD]
  float* Psm = smf + KS_F + VS_F;   // [128][KPAD]
  const uint32_t sb = s2u(smf);
  const uint32_t ks_b = sb;
  const uint32_t vs_b = sb + KS_F * 4;

  const int qt = blockIdx.x, h = blockIdx.y, b = blockIdx.z;
  const int g = h >> 2;
  const float* qb = qkv + (size_t)b * S_ * ASH_ + g * 384 + (h & 3) * 64;
  const float* kb = qkv + (size_t)b * S_ * ASH_ + g * 384 + 256;
  const int tid = threadIdx.x, wid = tid >> 5, lid = tid & 31;
  const int r = lid >> 2, cc = lid & 3;
  const int r0 = qt * 128;
  const int wrow = wid * 16;

  auto load_kv = [&](int kt, int st) {
#pragma unroll
    for (int c = 0; c < 4; c++) {
      int ch = tid + c * 256;
      int key = ch >> 4, d4 = ch & 15;
      const float* src = kb + (size_t)(kt * 64 + key) * ASH_ + d4 * 4;
      cpa16(ks_b + (uint32_t)(st * 64 * KPAD * 4 + key * (KPAD * 4) + d4 * 16),
            src);
      cpa16(vs_b + (uint32_t)(st * 64 * VPAD * 4 + key * (VPAD * 4) + d4 * 16),
            src + 64);  // vb = kb + 64
    }
  };

  // Q fragments: pre-rounded by rope; 0.125 scale is exact in tf32.
  uint32_t qf[8][4];
  {
    const float* q0 = qb + (size_t)(r0 + wrow + r) * ASH_;
    const float* q1 = q0 + 8 * ASH_;
#pragma unroll
    for (int ks = 0; ks < 8; ks++) {
      qf[ks][0] = __float_as_uint(0.125f * __ldg(q0 + ks * 8 + cc));
      qf[ks][1] = __float_as_uint(0.125f * __ldg(q1 + ks * 8 + cc));
      qf[ks][2] = __float_as_uint(0.125f * __ldg(q0 + ks * 8 + cc + 4));
      qf[ks][3] = __float_as_uint(0.125f * __ldg(q1 + ks * 8 + cc + 4));
    }
  }

  float m0r = -1e30f, m1r = -1e30f, l0 = 0.f, l1 = 0.f;
  float Oa[8][4];
#pragma unroll
  for (int nt = 0; nt < 8; nt++)
#pragma unroll
    for (int q = 0; q < 4; q++) Oa[nt][q] = 0.f;

  const int nkt = 2 * qt + 2;
  load_kv(0, 0);
  cpa_commit();

  for (int kt = 0; kt < nkt; kt++) {
    const int st = kt & 1;
    if (kt + 1 < nkt) {
      load_kv(kt + 1, st ^ 1);
      cpa_commit();
      cpa_wait<1>();
    } else {
      cpa_wait<0>();
    }
    __syncthreads();

    const float* Kt = Ksm + st * 64 * KPAD;
    const float* Vt = Vsm + st * 64 * VPAD;

    // S = Q K^T
    float Sa[8][4];
#pragma unroll
    for (int nt = 0; nt < 8; nt++)
#pragma unroll
      for (int q = 0; q < 4; q++) Sa[nt][q] = 0.f;
#pragma unroll
    for (int ks = 0; ks < 8; ks++) {
      uint32_t bf[8][2];
#pragma unroll
      for (int nt = 0; nt < 8; nt++) {
        const float* kp = Kt + (nt * 8 + r) * KPAD + ks * 8 + cc;
        bf[nt][0] = __float_as_uint(kp[0]);
        bf[nt][1] = __float_as_uint(kp[4]);
      }
#pragma unroll
      for (int nt = 0; nt < 8; nt++)
        mma_tf32_16x8x8(Sa[nt], qf[ks], bf[nt]);
    }

    // causal mask (only diagonal-crossing tiles)
    if (kt >= 2 * qt) {
      const int row_a = r0 + wrow + r, row_b = row_a + 8;
#pragma unroll
      for (int nt = 0; nt < 8; nt++) {
        int col = kt * 64 + nt * 8 + 2 * cc;
        if (col > row_a) Sa[nt][0] = -1e30f;
        if (col + 1 > row_a) Sa[nt][1] = -1e30f;
        if (col > row_b) Sa[nt][2] = -1e30f;
        if (col + 1 > row_b) Sa[nt][3] = -1e30f;
      }
    }

    // online softmax: rows r (regs 0,1) and r+8 (regs 2,3); 4 lanes/row.
    float mx0 = -1e30f, mx1 = -1e30f;
#pragma unroll
    for (int nt = 0; nt < 8; nt++) {
      mx0 = fmaxf(mx0, fmaxf(Sa[nt][0], Sa[nt][1]));
      mx1 = fmaxf(mx1, fmaxf(Sa[nt][2], Sa[nt][3]));
    }
#pragma unroll
    for (int d = 1; d <= 2; d <<= 1) {
      mx0 = fmaxf(mx0, __shfl_xor_sync(0xffffffffu, mx0, d));
      mx1 = fmaxf(mx1, __shfl_xor_sync(0xffffffffu, mx1, d));
    }
    float mn0 = fmaxf(m0r, mx0), mn1 = fmaxf(m1r, mx1);
    float al0 = __expf(m0r - mn0), al1 = __expf(m1r - mn1);
    m0r = mn0; m1r = mn1;
    float s0 = 0.f, s1 = 0.f;
#pragma unroll
    for (int nt = 0; nt < 8; nt++) {
      Sa[nt][0] = __expf(Sa[nt][0] - mn0); s0 += Sa[nt][0];
      Sa[nt][1] = __expf(Sa[nt][1] - mn0); s0 += Sa[nt][1];
      Sa[nt][2] = __expf(Sa[nt][2] - mn1); s1 += Sa[nt][2];
      Sa[nt][3] = __expf(Sa[nt][3] - mn1); s1 += Sa[nt][3];
    }
#pragma unroll
    for (int d = 1; d <= 2; d <<= 1) {
      s0 += __shfl_xor_sync(0xffffffffu, s0, d);
      s1 += __shfl_xor_sync(0xffffffffu, s1, d);
    }
    l0 = l0 * al0 + s0;
    l1 = l1 * al1 + s1;
#pragma unroll
    for (int nt = 0; nt < 8; nt++) {
      Oa[nt][0] *= al0; Oa[nt][1] *= al0;
      Oa[nt][2] *= al1; Oa[nt][3] *= al1;
    }

    // P -> per-warp smem relay (tf32-rounded)
    {
      float* pr = Psm + (wrow + r) * KPAD;
#pragma unroll
      for (int nt = 0; nt < 8; nt++) {
        float2 p01 = {to_tf32(Sa[nt][0]), to_tf32(Sa[nt][1])};
        float2 p23 = {to_tf32(Sa[nt][2]), to_tf32(Sa[nt][3])};
        *(float2*)(pr + nt * 8 + 2 * cc) = p01;
        *(float2*)(pr + 8 * KPAD + nt * 8 + 2 * cc) = p23;
      }
    }
    __syncwarp();

    // O += P V
#pragma unroll
    for (int ks = 0; ks < 8; ks++) {
      uint32_t pf[4];
      const float* pp = Psm + (wrow + r) * KPAD + ks * 8 + cc;
      pf[0] = __float_as_uint(pp[0]);
      pf[1] = __float_as_uint(pp[8 * KPAD]);
      pf[2] = __float_as_uint(pp[4]);
      pf[3] = __float_as_uint(pp[8 * KPAD + 4]);
      uint32_t vf[8][2];
#pragma unroll
      for (int nt = 0; nt < 8; nt++) {
        const float* vp = Vt + (ks * 8 + cc) * VPAD + nt * 8 + r;
        vf[nt][0] = __float_as_uint(vp[0]);
        vf[nt][1] = __float_as_uint(vp[4 * VPAD]);
      }
#pragma unroll
      for (int nt = 0; nt < 8; nt++)
        mma_tf32_16x8x8(Oa[nt], pf, vf[nt]);
    }
    __syncthreads();   // all warps done with stage st before it is refilled
  }

  // epilogue: normalize, round to tf32, store k-PERMUTED (out-proj operand A).
  // orig col within 8-group c -> pos 2c (c<4) else 2(c-4)+1.
  // thread holds cols 2cc, 2cc+1 -> positions pbase, pbase+2.
  const float inv0 = 1.f / l0, inv1 = 1.f / l1;
  const int pbase = (cc & 1) * 4 + (cc >> 1);
  float* ob = o + (size_t)(b * S_ + r0 + wrow + r) * DIM_ + h * 64;
#pragma unroll
  for (int nt = 0; nt < 8; nt++) {
    ob[nt * 8 + pbase] = to_tf32(Oa[nt][0] * inv0);
    ob[nt * 8 + pbase + 2] = to_tf32(Oa[nt][1] * inv0);
    ob[8 * DIM_ + nt * 8 + pbase] = to_tf32(Oa[nt][2] * inv1);
    ob[8 * DIM_ + nt * 8 + pbase + 2] = to_tf32(Oa[nt][3] * inv1);
  }
}

// ---------------------------------------------------------------------------
extern "C" void kernel_launch(void* const* d_in, const int* in_sizes, int n_in,
                              void* d_out, int out_size) {
  const float* x    = (const float*)d_in[0];
  const float* fc   = (const float*)d_in[1];
  const float* fs   = (const float*)d_in[2];
  const float* wqkv = (const float*)d_in[3];
  const float* wo   = (const float*)d_in[4];
  float* out = (float*)d_out;

  float *qkv_p, *o_p, *xr_p, *wqkvr_p, *wor_p;
  cudaGetSymbolAddress((void**)&qkv_p, g_qkv);
  cudaGetSymbolAddress((void**)&o_p, g_o);
  cudaGetSymbolAddress((void**)&xr_p, g_xr);
  cudaGetSymbolAddress((void**)&wqkvr_p, g_wqkvr);
  cudaGetSymbolAddress((void**)&wor_p, g_wor);

  cudaFuncSetAttribute(gemm_mma, cudaFuncAttributeMaxDynamicSharedMemorySize,
                       SMEM_TOT);
  cudaFuncSetAttribute(flash_mma, cudaFuncAttributeMaxDynamicSharedMemorySize,
                       ATTN_SMEM_B);

  // 0) round + k-permute GEMM operands (once; deletes all in-loop cvts)
  {
    int n8 = MTOT_ * DIM_ / 8;
    roundperm_kernel<<<(n8 + 255) / 256, 256>>>(x, xr_p, n8);
    n8 = ASH_ * DIM_ / 8;
    roundperm_kernel<<<(n8 + 255) / 256, 256>>>(wqkv, wqkvr_p, n8);
    n8 = DIM_ * DIM_ / 8;
    roundperm_kernel<<<(n8 + 255) / 256, 256>>>(wo, wor_p, n8);
  }

  // 1) QKV projection (mma.sync tf32, permuted operands)
  gemm_mma<<<dim3(ASH_ / BN, MTOT_ / BM), 256, SMEM_TOT>>>(xr_p, wqkvr_p,
                                                           qkv_p, ASH_);

  // 2) RoPE (+ tf32 rounding of q/k/v)
  {
    int total = MTOT_ * 48 * 32;
    rope_kernel<<<(total + 255) / 256, 256>>>(qkv_p, fc, fs);
  }

  // 3) causal GQA flash attention (mma.sync tf32)
  flash_mma<<<dim3(S_ / 128, NH_, B_), 256, ATTN_SMEM_B>>>(qkv_p, o_p);

  // 4) output projection (mma.sync tf32, permuted operands)
  gemm_mma<<<dim3(DIM_ / BN, MTOT_ / BM), 256, SMEM_TOT>>>(o_p, wor_p, out,
                                                           DIM_);
}

// round 16
// speedup vs baseline: 3.5707x; 1.0495x over previous
#include <cuda_runtime.h>
#include <cstdint>
#include <math.h>

#define B_    4
#define S_    1024
#define DIM_  2048
#define NH_   32
#define NKV_  8
#define HD_   64
#define ASH_  3072     // (32 + 2*8) * 64
#define MTOT_ 4096     // B_ * S_
#define KDIM_ 2048

// ---- mma.sync tf32 GEMM tiling ----
#define STAGES   4
#define BM       128
#define BN       256
#define BK       16
#define NIT      (KDIM_ / BK)        // 128
#define LDS_STR  24                  // padded smem stride (floats)
#define A_BYTES  (BM * LDS_STR * 4)  // 12288
#define B_BYTES  (BN * LDS_STR * 4)  // 24576
#define STG_BYTES (A_BYTES + B_BYTES)  // 36864
#define SMEM_TOT (STAGES * STG_BYTES)  // 147456

// ---- flash attention smem layout (floats) ----
#define KPAD  68
#define VPAD  72
#define KS_F  (2 * 64 * KPAD)        // 8704
#define VS_F  (2 * 64 * VPAD)        // 9216
#define PS_F  (128 * KPAD)           // 8704
#define ATTN_SMEM_B ((KS_F + VS_F + PS_F) * 4)  // 106496

// Scratch (allocation-free: __device__ globals)
__device__ float g_qkv[MTOT_ * ASH_];    // 48 MB (q/k/v tf32-rounded by rope)
__device__ float g_o[MTOT_ * DIM_];      // 32 MB (tf32-rounded + k-permuted)
__device__ float g_xr[MTOT_ * DIM_];     // 32 MB: rounded+permuted x
__device__ float g_wqkvr[ASH_ * DIM_];   // 24 MB: rounded+permuted wqkv
__device__ float g_wor[DIM_ * DIM_];     // 16 MB: rounded+permuted wo

// ---------------------------------------------------------------------------
// PTX helpers (sm_80-baseline only: cp.async + mma.sync + cvt.rna.tf32)
// ---------------------------------------------------------------------------
__device__ __forceinline__ uint32_t s2u(const void* p) {
  uint32_t a;
  asm("{ .reg .u64 t; cvta.to.shared.u64 t, %1; cvt.u32.u64 %0, t; }"
      : "=r"(a) : "l"(p));
  return a;
}
__device__ __forceinline__ float to_tf32(float x) {
  float y;
  asm("cvt.rna.tf32.f32 %0, %1;" : "=f"(y) : "f"(x));
  return y;
}
__device__ __forceinline__ void cpa16(uint32_t dst, const void* src) {
  asm volatile("cp.async.cg.shared.global [%0], [%1], 16;" :: "r"(dst), "l"(src));
}
__device__ __forceinline__ void cpa_commit() {
  asm volatile("cp.async.commit_group;" ::: "memory");
}
template <int N>
__device__ __forceinline__ void cpa_wait() {
  asm volatile("cp.async.wait_group %0;" :: "n"(N) : "memory");
}
__device__ __forceinline__ void mma_tf32_16x8x8(float* d, const uint32_t* a,
                                                const uint32_t* b) {
  asm volatile(
      "mma.sync.aligned.m16n8k8.row.col.f32.tf32.tf32.f32 "
      "{%0,%1,%2,%3}, {%4,%5,%6,%7}, {%8,%9}, {%0,%1,%2,%3};\n"
      : "+f"(d[0]), "+f"(d[1]), "+f"(d[2]), "+f"(d[3])
      : "r"(a[0]), "r"(a[1]), "r"(a[2]), "r"(a[3]), "r"(b[0]), "r"(b[1]));
}

// ---------------------------------------------------------------------------
// Round to tf32 (rna) and permute each k-8-group to [k0,k4,k1,k5,k2,k6,k3,k7]
// so mma fragment pairs (cc, cc+4) are contiguous in memory.
// ---------------------------------------------------------------------------
__global__ void roundperm_kernel(const float* __restrict__ src,
                                 float* __restrict__ dst, int n8) {
  int i = blockIdx.x * blockDim.x + threadIdx.x;
  if (i >= n8) return;
  const float4* s = (const float4*)src + (size_t)i * 2;
  float4 a = s[0], b = s[1];
  float4 c0 = {to_tf32(a.x), to_tf32(b.x), to_tf32(a.y), to_tf32(b.y)};
  float4 c1 = {to_tf32(a.z), to_tf32(b.z), to_tf32(a.w), to_tf32(b.w)};
  float4* d = (float4*)dst + (size_t)i * 2;
  d[0] = c0;
  d[1] = c1;
}

// ---------------------------------------------------------------------------
// mma.sync tf32 GEMM (NT): C[m][n] = sum_k A[m][k] * B[n][k]
// A and B pre-rounded + k-permuted. 128x256 block, BK=16, 256 threads =
// 8 warps (2M x 4N), warp tile 64x64 (32 MMAs per 16 LDS.64 per k8).
// 4-stage cp.async, 1 syncthreads per k-iter.
// ---------------------------------------------------------------------------
__global__ __launch_bounds__(256) void gemm_mma(const float* __restrict__ A,
                                                const float* __restrict__ B,
                                                float* __restrict__ C,
                                                int Ntot) {
  extern __shared__ float smf[];
  const uint32_t sb = s2u(smf);
  const int tid = threadIdx.x, wid = tid >> 5, lid = tid & 31;
  const int wm = wid & 1, wn = wid >> 1;     // 2 x 4 warp grid
  const int r = lid >> 2, cc = lid & 3;
  const int m0 = blockIdx.y * BM, n0 = blockIdx.x * BN;

  const float* Abase = A + (size_t)m0 * KDIM_;
  const float* Bbase = B + (size_t)n0 * KDIM_;

  auto load_tile = [&](int i) {
    uint32_t st = sb + (i % STAGES) * STG_BYTES;
    int k0 = i * BK;
#pragma unroll
    for (int c = 0; c < 2; c++) {     // A: 512 chunks of 16B
      int ch = tid + c * 256;
      int m = ch >> 2, kc = ch & 3;
      cpa16(st + (uint32_t)(m * (LDS_STR * 4) + kc * 16),
            Abase + (size_t)m * KDIM_ + k0 + kc * 4);
    }
#pragma unroll
    for (int c = 0; c < 4; c++) {     // B: 1024 chunks of 16B
      int ch = tid + c * 256;
      int n = ch >> 2, kc = ch & 3;
      cpa16(st + A_BYTES + (uint32_t)(n * (LDS_STR * 4) + kc * 16),
            Bbase + (size_t)n * KDIM_ + k0 + kc * 4);
    }
  };

  float acc[4][8][4];
#pragma unroll
  for (int mt = 0; mt < 4; mt++)
#pragma unroll
    for (int nt = 0; nt < 8; nt++)
#pragma unroll
      for (int q = 0; q < 4; q++) acc[mt][nt][q] = 0.f;

  // prologue: 3 tiles in flight
#pragma unroll
  for (int i = 0; i < STAGES - 1; i++) { load_tile(i); cpa_commit(); }

  for (int i = 0; i < NIT; i++) {
    int s = i % STAGES;
    cpa_wait<STAGES - 2>();
    __syncthreads();   // all warps done with slot (i-1)%STAGES, tile i ready

    int j = i + STAGES - 1;
    if (j < NIT) { load_tile(j); cpa_commit(); }

    const float* As = smf + s * (STG_BYTES / 4);
    const float* Bs = As + BM * LDS_STR;
#pragma unroll
    for (int ks = 0; ks < 2; ks++) {
      const int k = ks * 8;
      uint32_t af[4][4], bf[8][2];
#pragma unroll
      for (int mt = 0; mt < 4; mt++) {
        const float2 v0 =
            *(const float2*)(As + (wm * 64 + mt * 16 + r) * LDS_STR + k + 2 * cc);
        const float2 v1 =
            *(const float2*)(As + (wm * 64 + mt * 16 + r + 8) * LDS_STR + k + 2 * cc);
        af[mt][0] = __float_as_uint(v0.x);
        af[mt][1] = __float_as_uint(v1.x);
        af[mt][2] = __float_as_uint(v0.y);
        af[mt][3] = __float_as_uint(v1.y);
      }
#pragma unroll
      for (int nt = 0; nt < 8; nt++) {
        const float2 bv =
            *(const float2*)(Bs + (wn * 64 + nt * 8 + r) * LDS_STR + k + 2 * cc);
        bf[nt][0] = __float_as_uint(bv.x);
        bf[nt][1] = __float_as_uint(bv.y);
      }
#pragma unroll
      for (int mt = 0; mt < 4; mt++)
#pragma unroll
        for (int nt = 0; nt < 8; nt++)
          mma_tf32_16x8x8(acc[mt][nt], af[mt], bf[nt]);
    }
  }

  // epilogue
#pragma unroll
  for (int mt = 0; mt < 4; mt++) {
    int row0 = m0 + wm * 64 + mt * 16 + r;
#pragma unroll
    for (int nt = 0; nt < 8; nt++) {
      int col = n0 + wn * 64 + nt * 8 + cc * 2;
      float2 v01 = {acc[mt][nt][0], acc[mt][nt][1]};
      float2 v23 = {acc[mt][nt][2], acc[mt][nt][3]};
      *(float2*)(C + (size_t)row0 * Ntot + col) = v01;
      *(float2*)(C + (size_t)(row0 + 8) * Ntot + col) = v23;
    }
  }
}

// ---------------------------------------------------------------------------
// RoPE in-place on q (slots 0..3) and k (slot 4); v (slot 5) pass-through.
// ALL outputs tf32-rounded so flash_mma needs no cvt on Q/K/V.
// ---------------------------------------------------------------------------
__global__ void rope_kernel(float* __restrict__ qkv,
                            const float* __restrict__ cs,
                            const float* __restrict__ sn) {
  int p = blockIdx.x * blockDim.x + threadIdx.x;
  if (p >= MTOT_ * 48 * 32) return;
  int i = p & 31;
  int hh = (p >> 5) % 48;
  int m = p / (48 * 32);
  int s = m & (S_ - 1);
  int g = hh / 6, j = hh - g * 6;    // j: 0..3 q slots, 4 k, 5 v
  size_t base = (size_t)m * ASH_ + g * 384 + j * 64 + 2 * i;
  float2 v = *(float2*)(qkv + base);
  float2 o;
  if (j < 5) {
    float c = cs[s * 32 + i], si = sn[s * 32 + i];
    o.x = to_tf32(v.x * c - v.y * si);
    o.y = to_tf32(v.x * si + v.y * c);
  } else {
    o.x = to_tf32(v.x);
    o.y = to_tf32(v.y);
  }
  *(float2*)(qkv + base) = o;
}

// ---------------------------------------------------------------------------
// Tensor-core flash attention (causal, GQA), tf32 mma.sync.
// Q/K/V pre-rounded by rope => no cvt in the mainloop. Output written
// tf32-rounded AND k-permuted so it feeds gemm_mma directly as operand A.
// ---------------------------------------------------------------------------
__global__ __launch_bounds__(256) void flash_mma(const float* __restrict__ qkv,
                                                 float* __restrict__ o) {
  extern __shared__ float smf[];
  float* Ksm = smf;                 // [2][64][KPAD]
  float* Vsm = smf + KS_F;          // [2][64][VPAD]
  float* Psm = smf + KS_F + VS_F;   // [128][KPAD]
  const uint32_t sb = s2u(smf);
  const uint32_t ks_b = sb;
  const uint32_t vs_b = sb + KS_F * 4;

  const int qt = blockIdx.x, h = blockIdx.y, b = blockIdx.z;
  const int g = h >> 2;
  const float* qb = qkv + (size_t)b * S_ * ASH_ + g * 384 + (h & 3) * 64;
  const float* kb = qkv + (size_t)b * S_ * ASH_ + g * 384 + 256;
  const int tid = threadIdx.x, wid = tid >> 5, lid = tid & 31;
  const int r = lid >> 2, cc = lid & 3;
  const int r0 = qt * 128;
  const int wrow = wid * 16;

  auto load_kv = [&](int kt, int st) {
#pragma unroll
    for (int c = 0; c < 4; c++) {
      int ch = tid + c * 256;
      int key = ch >> 4, d4 = ch & 15;
      const float* src = kb + (size_t)(kt * 64 + key) * ASH_ + d4 * 4;
      cpa16(ks_b + (uint32_t)(st * 64 * KPAD * 4 + key * (KPAD * 4) + d4 * 16),
            src);
      cpa16(vs_b + (uint32_t)(st * 64 * VPAD * 4 + key * (VPAD * 4) + d4 * 16),
            src + 64);  // vb = kb + 64
    }
  };

  // Q fragments: pre-rounded by rope; 0.125 scale is exact in tf32.
  uint32_t qf[8][4];
  {
    const float* q0 = qb + (size_t)(r0 + wrow + r) * ASH_;
    const float* q1 = q0 + 8 * ASH_;
#pragma unroll
    for (int ks = 0; ks < 8; ks++) {
      qf[ks][0] = __float_as_uint(0.125f * __ldg(q0 + ks * 8 + cc));
      qf[ks][1] = __float_as_uint(0.125f * __ldg(q1 + ks * 8 + cc));
      qf[ks][2] = __float_as_uint(0.125f * __ldg(q0 + ks * 8 + cc + 4));
      qf[ks][3] = __float_as_uint(0.125f * __ldg(q1 + ks * 8 + cc + 4));
    }
  }

  float m0r = -1e30f, m1r = -1e30f, l0 = 0.f, l1 = 0.f;
  float Oa[8][4];
#pragma unroll
  for (int nt = 0; nt < 8; nt++)
#pragma unroll
    for (int q = 0; q < 4; q++) Oa[nt][q] = 0.f;

  const int nkt = 2 * qt + 2;
  load_kv(0, 0);
  cpa_commit();

  for (int kt = 0; kt < nkt; kt++) {
    const int st = kt & 1;
    if (kt + 1 < nkt) {
      load_kv(kt + 1, st ^ 1);
      cpa_commit();
      cpa_wait<1>();
    } else {
      cpa_wait<0>();
    }
    __syncthreads();

    const float* Kt = Ksm + st * 64 * KPAD;
    const float* Vt = Vsm + st * 64 * VPAD;

    // S = Q K^T
    float Sa[8][4];
#pragma unroll
    for (int nt = 0; nt < 8; nt++)
#pragma unroll
      for (int q = 0; q < 4; q++) Sa[nt][q] = 0.f;
#pragma unroll
    for (int ks = 0; ks < 8; ks++) {
      uint32_t bf[8][2];
#pragma unroll
      for (int nt = 0; nt < 8; nt++) {
        const float* kp = Kt + (nt * 8 + r) * KPAD + ks * 8 + cc;
        bf[nt][0] = __float_as_uint(kp[0]);
        bf[nt][1] = __float_as_uint(kp[4]);
      }
#pragma unroll
      for (int nt = 0; nt < 8; nt++)
        mma_tf32_16x8x8(Sa[nt], qf[ks], bf[nt]);
    }

    // causal mask (only diagonal-crossing tiles)
    if (kt >= 2 * qt) {
      const int row_a = r0 + wrow + r, row_b = row_a + 8;
#pragma unroll
      for (int nt = 0; nt < 8; nt++) {
        int col = kt * 64 + nt * 8 + 2 * cc;
        if (col > row_a) Sa[nt][0] = -1e30f;
        if (col + 1 > row_a) Sa[nt][1] = -1e30f;
        if (col > row_b) Sa[nt][2] = -1e30f;
        if (col + 1 > row_b) Sa[nt][3] = -1e30f;
      }
    }

    // online softmax: rows r (regs 0,1) and r+8 (regs 2,3); 4 lanes/row.
    float mx0 = -1e30f, mx1 = -1e30f;
#pragma unroll
    for (int nt = 0; nt < 8; nt++) {
      mx0 = fmaxf(mx0, fmaxf(Sa[nt][0], Sa[nt][1]));
      mx1 = fmaxf(mx1, fmaxf(Sa[nt][2], Sa[nt][3]));
    }
#pragma unroll
    for (int d = 1; d <= 2; d <<= 1) {
      mx0 = fmaxf(mx0, __shfl_xor_sync(0xffffffffu, mx0, d));
      mx1 = fmaxf(mx1, __shfl_xor_sync(0xffffffffu, mx1, d));
    }
    float mn0 = fmaxf(m0r, mx0), mn1 = fmaxf(m1r, mx1);
    float al0 = __expf(m0r - mn0), al1 = __expf(m1r - mn1);
    m0r = mn0; m1r = mn1;
    float s0 = 0.f, s1 = 0.f;
#pragma unroll
    for (int nt = 0; nt < 8; nt++) {
      Sa[nt][0] = __expf(Sa[nt][0] - mn0); s0 += Sa[nt][0];
      Sa[nt][1] = __expf(Sa[nt][1] - mn0); s0 += Sa[nt][1];
      Sa[nt][2] = __expf(Sa[nt][2] - mn1); s1 += Sa[nt][2];
      Sa[nt][3] = __expf(Sa[nt][3] - mn1); s1 += Sa[nt][3];
    }
#pragma unroll
    for (int d = 1; d <= 2; d <<= 1) {
      s0 += __shfl_xor_sync(0xffffffffu, s0, d);
      s1 += __shfl_xor_sync(0xffffffffu, s1, d);
    }
    l0 = l0 * al0 + s0;
    l1 = l1 * al1 + s1;
#pragma unroll
    for (int nt = 0; nt < 8; nt++) {
      Oa[nt][0] *= al0; Oa[nt][1] *= al0;
      Oa[nt][2] *= al1; Oa[nt][3] *= al1;
    }

    // P -> per-warp smem relay (tf32-rounded)
    {
      float* pr = Psm + (wrow + r) * KPAD;
#pragma unroll
      for (int nt = 0; nt < 8; nt++) {
        float2 p01 = {to_tf32(Sa[nt][0]), to_tf32(Sa[nt][1])};
        float2 p23 = {to_tf32(Sa[nt][2]), to_tf32(Sa[nt][3])};
        *(float2*)(pr + nt * 8 + 2 * cc) = p01;
        *(float2*)(pr + 8 * KPAD + nt * 8 + 2 * cc) = p23;
      }
    }
    __syncwarp();

    // O += P V
#pragma unroll
    for (int ks = 0; ks < 8; ks++) {
      uint32_t pf[4];
      const float* pp = Psm + (wrow + r) * KPAD + ks * 8 + cc;
      pf[0] = __float_as_uint(pp[0]);
      pf[1] = __float_as_uint(pp[8 * KPAD]);
      pf[2] = __float_as_uint(pp[4]);
      pf[3] = __float_as_uint(pp[8 * KPAD + 4]);
      uint32_t vf[8][2];
#pragma unroll
      for (int nt = 0; nt < 8; nt++) {
        const float* vp = Vt + (ks * 8 + cc) * VPAD + nt * 8 + r;
        vf[nt][0] = __float_as_uint(vp[0]);
        vf[nt][1] = __float_as_uint(vp[4 * VPAD]);
      }
#pragma unroll
      for (int nt = 0; nt < 8; nt++)
        mma_tf32_16x8x8(Oa[nt], pf, vf[nt]);
    }
    __syncthreads();   // all warps done with stage st before it is refilled
  }

  // epilogue: normalize, round to tf32, store k-PERMUTED (out-proj operand A).
  const float inv0 = 1.f / l0, inv1 = 1.f / l1;
  const int pbase = (cc & 1) * 4 + (cc >> 1);
  float* ob = o + (size_t)(b * S_ + r0 + wrow + r) * DIM_ + h * 64;
#pragma unroll
  for (int nt = 0; nt < 8; nt++) {
    ob[nt * 8 + pbase] = to_tf32(Oa[nt][0] * inv0);
    ob[nt * 8 + pbase + 2] = to_tf32(Oa[nt][1] * inv0);
    ob[8 * DIM_ + nt * 8 + pbase] = to_tf32(Oa[nt][2] * inv1);
    ob[8 * DIM_ + nt * 8 + pbase + 2] = to_tf32(Oa[nt][3] * inv1);
  }
}

// ---------------------------------------------------------------------------
extern "C" void kernel_launch(void* const* d_in, const int* in_sizes, int n_in,
                              void* d_out, int out_size) {
  const float* x    = (const float*)d_in[0];
  const float* fc   = (const float*)d_in[1];
  const float* fs   = (const float*)d_in[2];
  const float* wqkv = (const float*)d_in[3];
  const float* wo   = (const float*)d_in[4];
  float* out = (float*)d_out;

  float *qkv_p, *o_p, *xr_p, *wqkvr_p, *wor_p;
  cudaGetSymbolAddress((void**)&qkv_p, g_qkv);
  cudaGetSymbolAddress((void**)&o_p, g_o);
  cudaGetSymbolAddress((void**)&xr_p, g_xr);
  cudaGetSymbolAddress((void**)&wqkvr_p, g_wqkvr);
  cudaGetSymbolAddress((void**)&wor_p, g_wor);

  cudaFuncSetAttribute(gemm_mma, cudaFuncAttributeMaxDynamicSharedMemorySize,
                       SMEM_TOT);
  cudaFuncSetAttribute(flash_mma, cudaFuncAttributeMaxDynamicSharedMemorySize,
                       ATTN_SMEM_B);

  // 0) round + k-permute GEMM operands (once)
  {
    int n8 = MTOT_ * DIM_ / 8;
    roundperm_kernel<<<(n8 + 255) / 256, 256>>>(x, xr_p, n8);
    n8 = ASH_ * DIM_ / 8;
    roundperm_kernel<<<(n8 + 255) / 256, 256>>>(wqkv, wqkvr_p, n8);
    n8 = DIM_ * DIM_ / 8;
    roundperm_kernel<<<(n8 + 255) / 256, 256>>>(wo, wor_p, n8);
  }

  // 1) QKV projection (mma.sync tf32, 64x64 warp tiles)
  gemm_mma<<<dim3(ASH_ / BN, MTOT_ / BM), 256, SMEM_TOT>>>(xr_p, wqkvr_p,
                                                           qkv_p, ASH_);

  // 2) RoPE (+ tf32 rounding of q/k/v)
  {
    int total = MTOT_ * 48 * 32;
    rope_kernel<<<(total + 255) / 256, 256>>>(qkv_p, fc, fs);
  }

  // 3) causal GQA flash attention (mma.sync tf32)
  flash_mma<<<dim3(S_ / 128, NH_, B_), 256, ATTN_SMEM_B>>>(qkv_p, o_p);

  // 4) output projection (mma.sync tf32, 64x64 warp tiles)
  gemm_mma<<<dim3(DIM_ / BN, MTOT_ / BM), 256, SMEM_TOT>>>(o_p, wor_p, out,
                                                           DIM_);
}